// round 12
// baseline (speedup 1.0000x reference)
#include <cuda_runtime.h>

// Inverse 2D DWT, single level. (4,64,256,256) f32 x4 subbands -> (4,64,512,512) f32.
// Warp-autonomous, LDG.128 + deep front-batched prefetch:
//  - One warp owns a 128-col strip x 32 rows; each lane owns 4 adjacent columns
//    (one ulonglong2 per subband-row).
//  - 2 rows computed per iteration; ALL loads for the NEXT iteration (8 LDG.128
//    owned + 8 LDG.32 halo) are issued at the iteration top -> 16 loads (~2.3KB)
//    in flight per warp with ~190 instrs of cover.
//  - W-edge reflection in-lane; one interior halo column per strip.
//  - f32x2 FFMA math, shuffle row pass, float4 streaming stores. No smem/barriers.

#define HH 256
#define WW 256
#define RW 32
#define NT 64

typedef unsigned long long u64;

__device__ __forceinline__ u64 pk(float lo, float hi) {
    u64 r; asm("mov.b64 %0, {%1, %2};" : "=l"(r) : "f"(lo), "f"(hi)); return r;
}
__device__ __forceinline__ void unpk(u64 v, float& lo, float& hi) {
    asm("mov.b64 {%0, %1}, %2;" : "=f"(lo), "=f"(hi) : "l"(v));
}
__device__ __forceinline__ float lof(u64 v) { float a, b; unpk(v, a, b); return a; }
__device__ __forceinline__ float hif(u64 v) { float a, b; unpk(v, a, b); return b; }
__device__ __forceinline__ u64 ffma2(u64 a, u64 b, u64 c) {
    u64 d; asm("fma.rn.f32x2 %0, %1, %2, %3;" : "=l"(d) : "l"(a), "l"(b), "l"(c)); return d;
}
__device__ __forceinline__ u64 fmul2(u64 a, u64 b) {
    u64 d; asm("mul.rn.f32x2 %0, %1, %2;" : "=l"(d) : "l"(a), "l"(b)); return d;
}
__device__ __forceinline__ int reflH(int i) {
    return i < 0 ? -i : (i >= HH ? 2 * HH - 2 - i : i);
}
__device__ __forceinline__ float shup(float v) { return __shfl_up_sync(0xffffffffu, v, 1); }
__device__ __forceinline__ float shdn(float v) { return __shfl_down_sync(0xffffffffu, v, 1); }
__device__ __forceinline__ ulonglong2 ldg4(const float* __restrict__ p, int row) {
    return __ldcs((const ulonglong2*)(p + (size_t)row * WW));
}
__device__ __forceinline__ float ldg1(const float* __restrict__ p, int row, int dq) {
    return __ldcs(p + (size_t)row * WW + dq);
}

__global__ __launch_bounds__(NT, 6)
void idwt2d(const float* __restrict__ ss, const float* __restrict__ sd,
            const float* __restrict__ ds, const float* __restrict__ dd,
            const float* __restrict__ hf, const float* __restrict__ gf,
            float* __restrict__ out)
{
    const int lane  = threadIdx.x & 31;
    const int strip = threadIdx.x >> 5;               // 0: cols 0-127, 1: cols 128-255
    const int bc    = blockIdx.z;
    const int r0    = blockIdx.y * RW;
    const int c     = strip * 128 + 4 * lane;         // first of 4 owned columns
    const int dq    = (strip ? 127 : 128) - c;        // interior halo column offset

    const size_t base = (size_t)bc * (HH * WW);
    const float* __restrict__ pss = ss + base + c;
    const float* __restrict__ psd = sd + base + c;
    const float* __restrict__ pds = ds + base + c;
    const float* __restrict__ pdd = dd + base + c;
    float* __restrict__ pout = out + (size_t)bc * (4 * HH * WW) + 2 * c;

    u64 H0, H1, H2, H3, H4, H5, G0, G1, G2, G3, G4, G5;
    {
        const float a0 = hf[0], a1 = hf[1], a2 = hf[2], a3 = hf[3], a4 = hf[4], a5 = hf[5];
        const float b0 = gf[0], b1 = gf[1], b2 = gf[2], b3 = gf[3], b4 = gf[4], b5 = gf[5];
        H0 = pk(a0, a0); H1 = pk(a1, a1); H2 = pk(a2, a2);
        H3 = pk(a3, a3); H4 = pk(a4, a4); H5 = pk(a5, a5);
        G0 = pk(b0, b0); G1 = pk(b1, b1); G2 = pk(b2, b2);
        G3 = pk(b3, b3); G4 = pk(b4, b4); G5 = pk(b5, b5);
    }

    // 4-row window: slots 0..3 = rows r-1, r, r+1, r+2
    ulonglong2 S[4], T[4], U[4], V[4];
    float hs[4], ht[4], hu[4], hv[4];
    #pragma unroll
    for (int k = 0; k < 4; ++k) {
        const int rr = reflH(r0 - 1 + k);
        S[k] = ldg4(pss, rr); T[k] = ldg4(psd, rr);
        U[k] = ldg4(pds, rr); V[k] = ldg4(pdd, rr);
        hs[k] = ldg1(pss, rr, dq); ht[k] = ldg1(psd, rr, dq);
        hu[k] = ldg1(pds, rr, dq); hv[k] = ldg1(pdd, rr, dq);
    }

    #pragma unroll 2
    for (int i = 0; i < RW; i += 2) {
        const int r = r0 + i;

        // ---- front-batched prefetch for NEXT iteration: rows r+3, r+4 ----
        const int ra = reflH(r + 3), rb = reflH(r + 4);
        const ulonglong2 PS0 = ldg4(pss, ra), PT0 = ldg4(psd, ra);
        const ulonglong2 PU0 = ldg4(pds, ra), PV0 = ldg4(pdd, ra);
        const ulonglong2 PS1 = ldg4(pss, rb), PT1 = ldg4(psd, rb);
        const ulonglong2 PU1 = ldg4(pds, rb), PV1 = ldg4(pdd, rb);
        const float qsa = ldg1(pss, ra, dq), qta = ldg1(psd, ra, dq);
        const float qua = ldg1(pds, ra, dq), qva = ldg1(pdd, ra, dq);
        const float qsb = ldg1(pss, rb, dq), qtb = ldg1(psd, rb, dq);
        const float qub = ldg1(pds, rb, dq), qvb = ldg1(pdd, rb, dq);

        // ---- compute 2 owned rows from the current window ----
        #pragma unroll
        for (int k = 0; k < 2; ++k) {
            // column pass (4 arrays x 2 u64 halves)
            const u64 A0x = ffma2(H4, S[k].x, ffma2(H2, S[k+1].x, ffma2(H0, S[k+2].x,
                            ffma2(G4, T[k].x, ffma2(G2, T[k+1].x, fmul2(G0, T[k+2].x))))));
            const u64 A0y = ffma2(H4, S[k].y, ffma2(H2, S[k+1].y, ffma2(H0, S[k+2].y,
                            ffma2(G4, T[k].y, ffma2(G2, T[k+1].y, fmul2(G0, T[k+2].y))))));
            const u64 A1x = ffma2(H5, S[k].x, ffma2(H3, S[k+1].x, ffma2(H1, S[k+2].x,
                            ffma2(G5, T[k].x, ffma2(G3, T[k+1].x, fmul2(G1, T[k+2].x))))));
            const u64 A1y = ffma2(H5, S[k].y, ffma2(H3, S[k+1].y, ffma2(H1, S[k+2].y,
                            ffma2(G5, T[k].y, ffma2(G3, T[k+1].y, fmul2(G1, T[k+2].y))))));
            const u64 A2x = ffma2(H4, U[k].x, ffma2(H2, U[k+1].x, ffma2(H0, U[k+2].x,
                            ffma2(G4, V[k].x, ffma2(G2, V[k+1].x, fmul2(G0, V[k+2].x))))));
            const u64 A2y = ffma2(H4, U[k].y, ffma2(H2, U[k+1].y, ffma2(H0, U[k+2].y,
                            ffma2(G4, V[k].y, ffma2(G2, V[k+1].y, fmul2(G0, V[k+2].y))))));
            const u64 A3x = ffma2(H5, U[k].x, ffma2(H3, U[k+1].x, ffma2(H1, U[k+2].x,
                            ffma2(G5, V[k].x, ffma2(G3, V[k+1].x, fmul2(G1, V[k+2].x))))));
            const u64 A3y = ffma2(H5, U[k].y, ffma2(H3, U[k+1].y, ffma2(H1, U[k+2].y,
                            ffma2(G5, V[k].y, ffma2(G3, V[k+1].y, fmul2(G1, V[k+2].y))))));

            // halo column pass (packed pairwise: lo = s-side, hi = d-side)
            const u64 P0 = pk(hs[k],   hu[k]),   Q0 = pk(ht[k],   hv[k]);
            const u64 P1 = pk(hs[k+1], hu[k+1]), Q1 = pk(ht[k+1], hv[k+1]);
            const u64 P2 = pk(hs[k+2], hu[k+2]), Q2 = pk(ht[k+2], hv[k+2]);
            const u64 B02 = ffma2(H4, P0, ffma2(H2, P1, ffma2(H0, P2,
                            ffma2(G4, Q0, ffma2(G2, Q1, fmul2(G0, Q2))))));  // (b0,b2)
            const u64 B13 = ffma2(H5, P0, ffma2(H3, P1, ffma2(H1, P2,
                            ffma2(G5, Q0, ffma2(G3, Q1, fmul2(G1, Q2))))));  // (b1,b3)

            // row pass
            #pragma unroll
            for (int py = 0; py < 2; ++py) {
                const u64 Xa = py ? A1x : A0x, Xb = py ? A1y : A0y;   // sv: {x0,x1},{x2,x3}
                const u64 Ya = py ? A3x : A2x, Yb = py ? A3y : A2y;   // dv
                const u64 B  = py ? B13 : B02;
                const float hx = lof(B), hy = hif(B);

                float xm1 = shup(hif(Xb)); if (lane == 0)  xm1 = strip ? hx : hif(Xa);
                float xp4 = shdn(lof(Xa)); if (lane == 31) xp4 = strip ? lof(Xb) : hx;
                float ym1 = shup(hif(Yb)); if (lane == 0)  ym1 = strip ? hy : hif(Ya);
                float yp4 = shdn(lof(Ya)); if (lane == 31) yp4 = strip ? lof(Yb) : hy;

                const u64 AX = pk(xm1, lof(Xa));        // {x-1, x0}
                const u64 MX = pk(hif(Xa), lof(Xb));    // {x1, x2}
                const u64 CX = pk(hif(Xb), xp4);        // {x3, x4}
                const u64 AY = pk(ym1, lof(Ya));
                const u64 MY = pk(hif(Ya), lof(Yb));
                const u64 CY = pk(hif(Yb), yp4);

                const u64 pe01 = ffma2(H4, AX, ffma2(H2, Xa, ffma2(H0, MX,
                                 ffma2(G4, AY, ffma2(G2, Ya, fmul2(G0, MY))))));
                const u64 po01 = ffma2(H5, AX, ffma2(H3, Xa, ffma2(H1, MX,
                                 ffma2(G5, AY, ffma2(G3, Ya, fmul2(G1, MY))))));
                const u64 pe23 = ffma2(H4, MX, ffma2(H2, Xb, ffma2(H0, CX,
                                 ffma2(G4, MY, ffma2(G2, Yb, fmul2(G0, CY))))));
                const u64 po23 = ffma2(H5, MX, ffma2(H3, Xb, ffma2(H1, CX,
                                 ffma2(G5, MY, ffma2(G3, Yb, fmul2(G1, CY))))));

                float e0, e1, f0, f1;
                float* __restrict__ prow = pout + (size_t)(2 * (r + k) + py) * (2 * WW);
                unpk(pe01, e0, e1); unpk(po01, f0, f1);
                __stcs((float4*)prow, make_float4(e0, f0, e1, f1));
                unpk(pe23, e0, e1); unpk(po23, f0, f1);
                __stcs((float4*)(prow + 4), make_float4(e0, f0, e1, f1));
            }
        }

        // ---- roll window by 2 rows; prefetched rows land in slots 2,3 ----
        S[0] = S[2]; S[1] = S[3]; S[2] = PS0; S[3] = PS1;
        T[0] = T[2]; T[1] = T[3]; T[2] = PT0; T[3] = PT1;
        U[0] = U[2]; U[1] = U[3]; U[2] = PU0; U[3] = PU1;
        V[0] = V[2]; V[1] = V[3]; V[2] = PV0; V[3] = PV1;
        hs[0] = hs[2]; hs[1] = hs[3]; hs[2] = qsa; hs[3] = qsb;
        ht[0] = ht[2]; ht[1] = ht[3]; ht[2] = qta; ht[3] = qtb;
        hu[0] = hu[2]; hu[1] = hu[3]; hu[2] = qua; hu[3] = qub;
        hv[0] = hv[2]; hv[1] = hv[3]; hv[2] = qva; hv[3] = qvb;
    }
}

extern "C" void kernel_launch(void* const* d_in, const int* in_sizes, int n_in,
                              void* d_out, int out_size) {
    const float* ss = (const float*)d_in[0];
    const float* sd = (const float*)d_in[1];
    const float* ds = (const float*)d_in[2];
    const float* dd = (const float*)d_in[3];
    const float* h  = (const float*)d_in[4];
    const float* g  = (const float*)d_in[5];
    float* out = (float*)d_out;

    dim3 grid(1, HH / RW, 4 * 64);   // (1, 8, 256) = 2048 blocks x 2 warps
    idwt2d<<<grid, NT>>>(ss, sd, ds, dd, h, g, out);
}

// round 13
// speedup vs baseline: 1.1824x; 1.1824x over previous
#include <cuda_runtime.h>

// Inverse 2D DWT, single level. (4,64,256,256) f32 x4 subbands -> (4,64,512,512) f32.
// Warp-autonomous, LDG.128: one warp owns a 128-col strip x RW rows; each lane owns
// 4 adjacent columns (one ulonglong2 = 2 f32x2 per subband-row).
//  - Rolling 3-row window; next row loaded right after the column pass (hidden
//    under the row pass). Reads are 512B contiguous per warp-request, writes 1KB.
//  - W-edge reflection is in-lane; ONE interior halo column per strip (scalar).
//  - All math packed fp32x2 (FFMA2). No smem, no barriers.
//  - unroll 4 (~8KB loop body) to stay inside L0+L1.5 I$ (full unroll was ~33KB,
//    in the measured L2-I$ transition band).

#define HH 256
#define WW 256
#define RW 16
#define NT 128

typedef unsigned long long u64;

__device__ __forceinline__ u64 pk(float lo, float hi) {
    u64 r; asm("mov.b64 %0, {%1, %2};" : "=l"(r) : "f"(lo), "f"(hi)); return r;
}
__device__ __forceinline__ void unpk(u64 v, float& lo, float& hi) {
    asm("mov.b64 {%0, %1}, %2;" : "=f"(lo), "=f"(hi) : "l"(v));
}
__device__ __forceinline__ float lof(u64 v) { float a, b; unpk(v, a, b); return a; }
__device__ __forceinline__ float hif(u64 v) { float a, b; unpk(v, a, b); return b; }
__device__ __forceinline__ u64 ffma2(u64 a, u64 b, u64 c) {
    u64 d; asm("fma.rn.f32x2 %0, %1, %2, %3;" : "=l"(d) : "l"(a), "l"(b), "l"(c)); return d;
}
__device__ __forceinline__ u64 fmul2(u64 a, u64 b) {
    u64 d; asm("mul.rn.f32x2 %0, %1, %2;" : "=l"(d) : "l"(a), "l"(b)); return d;
}
__device__ __forceinline__ int reflH(int i) {
    return i < 0 ? -i : (i >= HH ? 2 * HH - 2 - i : i);
}
__device__ __forceinline__ float shup(float v) { return __shfl_up_sync(0xffffffffu, v, 1); }
__device__ __forceinline__ float shdn(float v) { return __shfl_down_sync(0xffffffffu, v, 1); }
__device__ __forceinline__ ulonglong2 ldg4(const float* __restrict__ p, int row) {
    return __ldcs((const ulonglong2*)(p + (size_t)row * WW));
}
__device__ __forceinline__ float ldg1(const float* __restrict__ p, int row, int dq) {
    return __ldcs(p + (size_t)row * WW + dq);
}

__global__ __launch_bounds__(NT, 4)
void idwt2d(const float* __restrict__ ss, const float* __restrict__ sd,
            const float* __restrict__ ds, const float* __restrict__ dd,
            const float* __restrict__ hf, const float* __restrict__ gf,
            float* __restrict__ out)
{
    const int lane  = threadIdx.x & 31;
    const int wid   = threadIdx.x >> 5;
    const int strip = wid & 1;                        // 0: cols 0-127, 1: cols 128-255
    const int bc    = blockIdx.z;
    const int r0    = blockIdx.y * (2 * RW) + (wid >> 1) * RW;
    const int c     = strip * 128 + 4 * lane;         // first of 4 owned columns
    const int dq    = (strip ? 127 : 128) - c;        // interior halo column offset

    const size_t base = (size_t)bc * (HH * WW);
    const float* __restrict__ pss = ss + base + c;
    const float* __restrict__ psd = sd + base + c;
    const float* __restrict__ pds = ds + base + c;
    const float* __restrict__ pdd = dd + base + c;
    float* __restrict__ pout = out + (size_t)bc * (4 * HH * WW) + 2 * c;

    u64 H0, H1, H2, H3, H4, H5, G0, G1, G2, G3, G4, G5;
    {
        const float a0 = hf[0], a1 = hf[1], a2 = hf[2], a3 = hf[3], a4 = hf[4], a5 = hf[5];
        const float b0 = gf[0], b1 = gf[1], b2 = gf[2], b3 = gf[3], b4 = gf[4], b5 = gf[5];
        H0 = pk(a0, a0); H1 = pk(a1, a1); H2 = pk(a2, a2);
        H3 = pk(a3, a3); H4 = pk(a4, a4); H5 = pk(a5, a5);
        G0 = pk(b0, b0); G1 = pk(b1, b1); G2 = pk(b2, b2);
        G3 = pk(b3, b3); G4 = pk(b4, b4); G5 = pk(b5, b5);
    }

    // 3-row window: a = row r-1, b = row r, c-slot = row r+1
    ulonglong2 Sa, Sb, Sc, Ta, Tb, Tc, Ua, Ub, Uc, Va, Vb, Vc;
    float hsa, hsb, hsc, hta, htb, htc, hua, hub, huc, hva, hvb, hvc;
    {
        const int rm = reflH(r0 - 1);
        Sa = ldg4(pss, rm); Ta = ldg4(psd, rm); Ua = ldg4(pds, rm); Va = ldg4(pdd, rm);
        hsa = ldg1(pss, rm, dq); hta = ldg1(psd, rm, dq);
        hua = ldg1(pds, rm, dq); hva = ldg1(pdd, rm, dq);
        Sb = ldg4(pss, r0); Tb = ldg4(psd, r0); Ub = ldg4(pds, r0); Vb = ldg4(pdd, r0);
        hsb = ldg1(pss, r0, dq); htb = ldg1(psd, r0, dq);
        hub = ldg1(pds, r0, dq); hvb = ldg1(pdd, r0, dq);
        Sc = ldg4(pss, r0 + 1); Tc = ldg4(psd, r0 + 1); Uc = ldg4(pds, r0 + 1); Vc = ldg4(pdd, r0 + 1);
        hsc = ldg1(pss, r0 + 1, dq); htc = ldg1(psd, r0 + 1, dq);
        huc = ldg1(pds, r0 + 1, dq); hvc = ldg1(pdd, r0 + 1, dq);
    }

    #pragma unroll 4
    for (int i = 0; i < RW; ++i) {
        const int r = r0 + i;

        // ---- column pass (4 arrays x 2 u64 halves) ----
        const u64 A0x = ffma2(H4, Sa.x, ffma2(H2, Sb.x, ffma2(H0, Sc.x,
                        ffma2(G4, Ta.x, ffma2(G2, Tb.x, fmul2(G0, Tc.x))))));
        const u64 A0y = ffma2(H4, Sa.y, ffma2(H2, Sb.y, ffma2(H0, Sc.y,
                        ffma2(G4, Ta.y, ffma2(G2, Tb.y, fmul2(G0, Tc.y))))));
        const u64 A1x = ffma2(H5, Sa.x, ffma2(H3, Sb.x, ffma2(H1, Sc.x,
                        ffma2(G5, Ta.x, ffma2(G3, Tb.x, fmul2(G1, Tc.x))))));
        const u64 A1y = ffma2(H5, Sa.y, ffma2(H3, Sb.y, ffma2(H1, Sc.y,
                        ffma2(G5, Ta.y, ffma2(G3, Tb.y, fmul2(G1, Tc.y))))));
        const u64 A2x = ffma2(H4, Ua.x, ffma2(H2, Ub.x, ffma2(H0, Uc.x,
                        ffma2(G4, Va.x, ffma2(G2, Vb.x, fmul2(G0, Vc.x))))));
        const u64 A2y = ffma2(H4, Ua.y, ffma2(H2, Ub.y, ffma2(H0, Uc.y,
                        ffma2(G4, Va.y, ffma2(G2, Vb.y, fmul2(G0, Vc.y))))));
        const u64 A3x = ffma2(H5, Ua.x, ffma2(H3, Ub.x, ffma2(H1, Uc.x,
                        ffma2(G5, Va.x, ffma2(G3, Vb.x, fmul2(G1, Vc.x))))));
        const u64 A3y = ffma2(H5, Ua.y, ffma2(H3, Ub.y, ffma2(H1, Uc.y,
                        ffma2(G5, Va.y, ffma2(G3, Vb.y, fmul2(G1, Vc.y))))));

        // halo column pass (packed pairwise: lo = s-side, hi = d-side)
        const u64 P0 = pk(hsa, hua), Q0 = pk(hta, hva);
        const u64 P1 = pk(hsb, hub), Q1 = pk(htb, hvb);
        const u64 P2 = pk(hsc, huc), Q2 = pk(htc, hvc);
        const u64 B02 = ffma2(H4, P0, ffma2(H2, P1, ffma2(H0, P2,
                        ffma2(G4, Q0, ffma2(G2, Q1, fmul2(G0, Q2))))));   // (b0, b2)
        const u64 B13 = ffma2(H5, P0, ffma2(H3, P1, ffma2(H1, P2,
                        ffma2(G5, Q0, ffma2(G3, Q1, fmul2(G1, Q2))))));   // (b1, b3)

        // ---- roll window + load next row (consumed next iteration) ----
        Sa = Sb; Sb = Sc; Ta = Tb; Tb = Tc;
        Ua = Ub; Ub = Uc; Va = Vb; Vb = Vc;
        hsa = hsb; hsb = hsc; hta = htb; htb = htc;
        hua = hub; hub = huc; hva = hvb; hvb = hvc;
        if (i != RW - 1) {
            const int rn = reflH(r + 2);
            Sc = ldg4(pss, rn); Tc = ldg4(psd, rn);
            Uc = ldg4(pds, rn); Vc = ldg4(pdd, rn);
            hsc = ldg1(pss, rn, dq); htc = ldg1(psd, rn, dq);
            huc = ldg1(pds, rn, dq); hvc = ldg1(pdd, rn, dq);
        }

        // ---- row pass ----
        #pragma unroll
        for (int py = 0; py < 2; ++py) {
            const u64 Xa = py ? A1x : A0x, Xb = py ? A1y : A0y;   // sv: {x0,x1},{x2,x3}
            const u64 Ya = py ? A3x : A2x, Yb = py ? A3y : A2y;   // dv
            const u64 B  = py ? B13 : B02;
            const float hx = lof(B), hy = hif(B);

            // v[c-1]: from lane-1's x3; strip0 lane0 -> in-lane v[1], strip1 lane0 -> halo
            float xm1 = shup(hif(Xb)); if (lane == 0)  xm1 = strip ? hx : hif(Xa);
            // v[c+4]: from lane+1's x0; strip0 lane31 -> halo, strip1 lane31 -> in-lane v[254]
            float xp4 = shdn(lof(Xa)); if (lane == 31) xp4 = strip ? lof(Xb) : hx;
            float ym1 = shup(hif(Yb)); if (lane == 0)  ym1 = strip ? hy : hif(Ya);
            float yp4 = shdn(lof(Ya)); if (lane == 31) yp4 = strip ? lof(Yb) : hy;

            const u64 AX = pk(xm1, lof(Xa));        // {x-1, x0}
            const u64 MX = pk(hif(Xa), lof(Xb));    // {x1, x2}  (C of pair01 == A of pair23)
            const u64 CX = pk(hif(Xb), xp4);        // {x3, x4}
            const u64 AY = pk(ym1, lof(Ya));
            const u64 MY = pk(hif(Ya), lof(Yb));
            const u64 CY = pk(hif(Yb), yp4);

            const u64 pe01 = ffma2(H4, AX, ffma2(H2, Xa, ffma2(H0, MX,
                             ffma2(G4, AY, ffma2(G2, Ya, fmul2(G0, MY))))));
            const u64 po01 = ffma2(H5, AX, ffma2(H3, Xa, ffma2(H1, MX,
                             ffma2(G5, AY, ffma2(G3, Ya, fmul2(G1, MY))))));
            const u64 pe23 = ffma2(H4, MX, ffma2(H2, Xb, ffma2(H0, CX,
                             ffma2(G4, MY, ffma2(G2, Yb, fmul2(G0, CY))))));
            const u64 po23 = ffma2(H5, MX, ffma2(H3, Xb, ffma2(H1, CX,
                             ffma2(G5, MY, ffma2(G3, Yb, fmul2(G1, CY))))));

            float e0, e1, f0, f1;
            float* __restrict__ prow = pout + (size_t)(2 * r + py) * (2 * WW);
            unpk(pe01, e0, e1); unpk(po01, f0, f1);
            __stcs((float4*)prow, make_float4(e0, f0, e1, f1));
            unpk(pe23, e0, e1); unpk(po23, f0, f1);
            __stcs((float4*)(prow + 4), make_float4(e0, f0, e1, f1));
        }
    }
}

extern "C" void kernel_launch(void* const* d_in, const int* in_sizes, int n_in,
                              void* d_out, int out_size) {
    const float* ss = (const float*)d_in[0];
    const float* sd = (const float*)d_in[1];
    const float* ds = (const float*)d_in[2];
    const float* dd = (const float*)d_in[3];
    const float* h  = (const float*)d_in[4];
    const float* g  = (const float*)d_in[5];
    float* out = (float*)d_out;

    dim3 grid(1, HH / (2 * RW), 4 * 64);   // (1, 8, 256) = 2048 blocks x 4 warps
    idwt2d<<<grid, NT>>>(ss, sd, ds, dd, h, g, out);
}

// round 14
// speedup vs baseline: 1.2822x; 1.0844x over previous
#include <cuda_runtime.h>

// Inverse 2D DWT, single level. (4,64,256,256) f32 x4 subbands -> (4,64,512,512) f32.
// Warp-autonomous, LDG.128 (champion R9 config): one warp owns a 128-col strip x RW
// rows; each lane owns 4 adjacent columns (one ulonglong2 = 2 f32x2 per subband-row).
//  - Rolling 3-row window; next row loaded right after the column pass.
//  - W-edge reflection in-lane; ONE interior halo column per strip (scalar loads).
//  - All math packed fp32x2 (FFMA2). No smem, no barriers. FULL unroll (validated).
//  - Cache policy: loads .cs (touch-once, evict early -> frees L2 capacity),
//    stores DEFAULT write-back (L2 acts as write-combining buffer, smoothing
//    DRAM read/write turnaround).

#define HH 256
#define WW 256
#define RW 16
#define NT 128

typedef unsigned long long u64;

__device__ __forceinline__ u64 pk(float lo, float hi) {
    u64 r; asm("mov.b64 %0, {%1, %2};" : "=l"(r) : "f"(lo), "f"(hi)); return r;
}
__device__ __forceinline__ void unpk(u64 v, float& lo, float& hi) {
    asm("mov.b64 {%0, %1}, %2;" : "=f"(lo), "=f"(hi) : "l"(v));
}
__device__ __forceinline__ float lof(u64 v) { float a, b; unpk(v, a, b); return a; }
__device__ __forceinline__ float hif(u64 v) { float a, b; unpk(v, a, b); return b; }
__device__ __forceinline__ u64 ffma2(u64 a, u64 b, u64 c) {
    u64 d; asm("fma.rn.f32x2 %0, %1, %2, %3;" : "=l"(d) : "l"(a), "l"(b), "l"(c)); return d;
}
__device__ __forceinline__ u64 fmul2(u64 a, u64 b) {
    u64 d; asm("mul.rn.f32x2 %0, %1, %2;" : "=l"(d) : "l"(a), "l"(b)); return d;
}
__device__ __forceinline__ int reflH(int i) {
    return i < 0 ? -i : (i >= HH ? 2 * HH - 2 - i : i);
}
__device__ __forceinline__ float shup(float v) { return __shfl_up_sync(0xffffffffu, v, 1); }
__device__ __forceinline__ float shdn(float v) { return __shfl_down_sync(0xffffffffu, v, 1); }
__device__ __forceinline__ ulonglong2 ldg4(const float* __restrict__ p, int row) {
    return __ldcs((const ulonglong2*)(p + (size_t)row * WW));
}
__device__ __forceinline__ float ldg1(const float* __restrict__ p, int row, int dq) {
    return __ldcs(p + (size_t)row * WW + dq);
}

__global__ __launch_bounds__(NT, 4)
void idwt2d(const float* __restrict__ ss, const float* __restrict__ sd,
            const float* __restrict__ ds, const float* __restrict__ dd,
            const float* __restrict__ hf, const float* __restrict__ gf,
            float* __restrict__ out)
{
    const int lane  = threadIdx.x & 31;
    const int wid   = threadIdx.x >> 5;
    const int strip = wid & 1;                        // 0: cols 0-127, 1: cols 128-255
    const int bc    = blockIdx.z;
    const int r0    = blockIdx.y * (2 * RW) + (wid >> 1) * RW;
    const int c     = strip * 128 + 4 * lane;         // first of 4 owned columns
    const int dq    = (strip ? 127 : 128) - c;        // interior halo column offset

    const size_t base = (size_t)bc * (HH * WW);
    const float* __restrict__ pss = ss + base + c;
    const float* __restrict__ psd = sd + base + c;
    const float* __restrict__ pds = ds + base + c;
    const float* __restrict__ pdd = dd + base + c;
    float* __restrict__ pout = out + (size_t)bc * (4 * HH * WW) + 2 * c;

    u64 H0, H1, H2, H3, H4, H5, G0, G1, G2, G3, G4, G5;
    {
        const float a0 = hf[0], a1 = hf[1], a2 = hf[2], a3 = hf[3], a4 = hf[4], a5 = hf[5];
        const float b0 = gf[0], b1 = gf[1], b2 = gf[2], b3 = gf[3], b4 = gf[4], b5 = gf[5];
        H0 = pk(a0, a0); H1 = pk(a1, a1); H2 = pk(a2, a2);
        H3 = pk(a3, a3); H4 = pk(a4, a4); H5 = pk(a5, a5);
        G0 = pk(b0, b0); G1 = pk(b1, b1); G2 = pk(b2, b2);
        G3 = pk(b3, b3); G4 = pk(b4, b4); G5 = pk(b5, b5);
    }

    // 3-row window: a = row r-1, b = row r, c-slot = row r+1
    ulonglong2 Sa, Sb, Sc, Ta, Tb, Tc, Ua, Ub, Uc, Va, Vb, Vc;
    float hsa, hsb, hsc, hta, htb, htc, hua, hub, huc, hva, hvb, hvc;
    {
        const int rm = reflH(r0 - 1);
        Sa = ldg4(pss, rm); Ta = ldg4(psd, rm); Ua = ldg4(pds, rm); Va = ldg4(pdd, rm);
        hsa = ldg1(pss, rm, dq); hta = ldg1(psd, rm, dq);
        hua = ldg1(pds, rm, dq); hva = ldg1(pdd, rm, dq);
        Sb = ldg4(pss, r0); Tb = ldg4(psd, r0); Ub = ldg4(pds, r0); Vb = ldg4(pdd, r0);
        hsb = ldg1(pss, r0, dq); htb = ldg1(psd, r0, dq);
        hub = ldg1(pds, r0, dq); hvb = ldg1(pdd, r0, dq);
        Sc = ldg4(pss, r0 + 1); Tc = ldg4(psd, r0 + 1); Uc = ldg4(pds, r0 + 1); Vc = ldg4(pdd, r0 + 1);
        hsc = ldg1(pss, r0 + 1, dq); htc = ldg1(psd, r0 + 1, dq);
        huc = ldg1(pds, r0 + 1, dq); hvc = ldg1(pdd, r0 + 1, dq);
    }

    #pragma unroll
    for (int i = 0; i < RW; ++i) {
        const int r = r0 + i;

        // ---- column pass (4 arrays x 2 u64 halves) ----
        const u64 A0x = ffma2(H4, Sa.x, ffma2(H2, Sb.x, ffma2(H0, Sc.x,
                        ffma2(G4, Ta.x, ffma2(G2, Tb.x, fmul2(G0, Tc.x))))));
        const u64 A0y = ffma2(H4, Sa.y, ffma2(H2, Sb.y, ffma2(H0, Sc.y,
                        ffma2(G4, Ta.y, ffma2(G2, Tb.y, fmul2(G0, Tc.y))))));
        const u64 A1x = ffma2(H5, Sa.x, ffma2(H3, Sb.x, ffma2(H1, Sc.x,
                        ffma2(G5, Ta.x, ffma2(G3, Tb.x, fmul2(G1, Tc.x))))));
        const u64 A1y = ffma2(H5, Sa.y, ffma2(H3, Sb.y, ffma2(H1, Sc.y,
                        ffma2(G5, Ta.y, ffma2(G3, Tb.y, fmul2(G1, Tc.y))))));
        const u64 A2x = ffma2(H4, Ua.x, ffma2(H2, Ub.x, ffma2(H0, Uc.x,
                        ffma2(G4, Va.x, ffma2(G2, Vb.x, fmul2(G0, Vc.x))))));
        const u64 A2y = ffma2(H4, Ua.y, ffma2(H2, Ub.y, ffma2(H0, Uc.y,
                        ffma2(G4, Va.y, ffma2(G2, Vb.y, fmul2(G0, Vc.y))))));
        const u64 A3x = ffma2(H5, Ua.x, ffma2(H3, Ub.x, ffma2(H1, Uc.x,
                        ffma2(G5, Va.x, ffma2(G3, Vb.x, fmul2(G1, Vc.x))))));
        const u64 A3y = ffma2(H5, Ua.y, ffma2(H3, Ub.y, ffma2(H1, Uc.y,
                        ffma2(G5, Va.y, ffma2(G3, Vb.y, fmul2(G1, Vc.y))))));

        // halo column pass (packed pairwise: lo = s-side, hi = d-side)
        const u64 P0 = pk(hsa, hua), Q0 = pk(hta, hva);
        const u64 P1 = pk(hsb, hub), Q1 = pk(htb, hvb);
        const u64 P2 = pk(hsc, huc), Q2 = pk(htc, hvc);
        const u64 B02 = ffma2(H4, P0, ffma2(H2, P1, ffma2(H0, P2,
                        ffma2(G4, Q0, ffma2(G2, Q1, fmul2(G0, Q2))))));   // (b0, b2)
        const u64 B13 = ffma2(H5, P0, ffma2(H3, P1, ffma2(H1, P2,
                        ffma2(G5, Q0, ffma2(G3, Q1, fmul2(G1, Q2))))));   // (b1, b3)

        // ---- roll window + load next row (consumed next iteration) ----
        Sa = Sb; Sb = Sc; Ta = Tb; Tb = Tc;
        Ua = Ub; Ub = Uc; Va = Vb; Vb = Vc;
        hsa = hsb; hsb = hsc; hta = htb; htb = htc;
        hua = hub; hub = huc; hva = hvb; hvb = hvc;
        if (i != RW - 1) {
            const int rn = reflH(r + 2);
            Sc = ldg4(pss, rn); Tc = ldg4(psd, rn);
            Uc = ldg4(pds, rn); Vc = ldg4(pdd, rn);
            hsc = ldg1(pss, rn, dq); htc = ldg1(psd, rn, dq);
            huc = ldg1(pds, rn, dq); hvc = ldg1(pdd, rn, dq);
        }

        // ---- row pass ----
        #pragma unroll
        for (int py = 0; py < 2; ++py) {
            const u64 Xa = py ? A1x : A0x, Xb = py ? A1y : A0y;   // sv: {x0,x1},{x2,x3}
            const u64 Ya = py ? A3x : A2x, Yb = py ? A3y : A2y;   // dv
            const u64 B  = py ? B13 : B02;
            const float hx = lof(B), hy = hif(B);

            // v[c-1]: from lane-1's x3; strip0 lane0 -> in-lane v[1], strip1 lane0 -> halo
            float xm1 = shup(hif(Xb)); if (lane == 0)  xm1 = strip ? hx : hif(Xa);
            // v[c+4]: from lane+1's x0; strip0 lane31 -> halo, strip1 lane31 -> in-lane v[254]
            float xp4 = shdn(lof(Xa)); if (lane == 31) xp4 = strip ? lof(Xb) : hx;
            float ym1 = shup(hif(Yb)); if (lane == 0)  ym1 = strip ? hy : hif(Ya);
            float yp4 = shdn(lof(Ya)); if (lane == 31) yp4 = strip ? lof(Yb) : hy;

            const u64 AX = pk(xm1, lof(Xa));        // {x-1, x0}
            const u64 MX = pk(hif(Xa), lof(Xb));    // {x1, x2}  (C of pair01 == A of pair23)
            const u64 CX = pk(hif(Xb), xp4);        // {x3, x4}
            const u64 AY = pk(ym1, lof(Ya));
            const u64 MY = pk(hif(Ya), lof(Yb));
            const u64 CY = pk(hif(Yb), yp4);

            const u64 pe01 = ffma2(H4, AX, ffma2(H2, Xa, ffma2(H0, MX,
                             ffma2(G4, AY, ffma2(G2, Ya, fmul2(G0, MY))))));
            const u64 po01 = ffma2(H5, AX, ffma2(H3, Xa, ffma2(H1, MX,
                             ffma2(G5, AY, ffma2(G3, Ya, fmul2(G1, MY))))));
            const u64 pe23 = ffma2(H4, MX, ffma2(H2, Xb, ffma2(H0, CX,
                             ffma2(G4, MY, ffma2(G2, Yb, fmul2(G0, CY))))));
            const u64 po23 = ffma2(H5, MX, ffma2(H3, Xb, ffma2(H1, CX,
                             ffma2(G5, MY, ffma2(G3, Yb, fmul2(G1, CY))))));

            // default (write-back) stores: L2 buffers writes, smoothing DRAM turnaround
            float e0, e1, f0, f1;
            float* __restrict__ prow = pout + (size_t)(2 * r + py) * (2 * WW);
            unpk(pe01, e0, e1); unpk(po01, f0, f1);
            *(float4*)prow = make_float4(e0, f0, e1, f1);
            unpk(pe23, e0, e1); unpk(po23, f0, f1);
            *(float4*)(prow + 4) = make_float4(e0, f0, e1, f1);
        }
    }
}

extern "C" void kernel_launch(void* const* d_in, const int* in_sizes, int n_in,
                              void* d_out, int out_size) {
    const float* ss = (const float*)d_in[0];
    const float* sd = (const float*)d_in[1];
    const float* ds = (const float*)d_in[2];
    const float* dd = (const float*)d_in[3];
    const float* h  = (const float*)d_in[4];
    const float* g  = (const float*)d_in[5];
    float* out = (float*)d_out;

    dim3 grid(1, HH / (2 * RW), 4 * 64);   // (1, 8, 256) = 2048 blocks x 4 warps
    idwt2d<<<grid, NT>>>(ss, sd, ds, dd, h, g, out);
}

// round 15
// speedup vs baseline: 1.2972x; 1.0117x over previous
#include <cuda_runtime.h>

// Inverse 2D DWT, single level. (4,64,256,256) f32 x4 subbands -> (4,64,512,512) f32.
// FINAL (champion R9 config + halo cache-policy fix):
// Warp-autonomous, LDG.128: one warp owns a 128-col strip x RW rows; each lane owns
// 4 adjacent columns (one ulonglong2 = 2 f32x2 per subband-row).
//  - Rolling 3-row window; next row loaded right after the column pass (hidden
//    under the row pass). Reads 512B contiguous per warp-request, writes 1KB.
//  - W-edge reflection in-lane; ONE interior halo column per strip. Halo loads use
//    DEFAULT caching (shared with the neighboring strip's warp -> L2 hit), owned
//    loads + stores use .cs streaming (touch-once).
//  - All math packed fp32x2 (FFMA2). No smem, no barriers. Full unroll.

#define HH 256
#define WW 256
#define RW 16
#define NT 128

typedef unsigned long long u64;

__device__ __forceinline__ u64 pk(float lo, float hi) {
    u64 r; asm("mov.b64 %0, {%1, %2};" : "=l"(r) : "f"(lo), "f"(hi)); return r;
}
__device__ __forceinline__ void unpk(u64 v, float& lo, float& hi) {
    asm("mov.b64 {%0, %1}, %2;" : "=f"(lo), "=f"(hi) : "l"(v));
}
__device__ __forceinline__ float lof(u64 v) { float a, b; unpk(v, a, b); return a; }
__device__ __forceinline__ float hif(u64 v) { float a, b; unpk(v, a, b); return b; }
__device__ __forceinline__ u64 ffma2(u64 a, u64 b, u64 c) {
    u64 d; asm("fma.rn.f32x2 %0, %1, %2, %3;" : "=l"(d) : "l"(a), "l"(b), "l"(c)); return d;
}
__device__ __forceinline__ u64 fmul2(u64 a, u64 b) {
    u64 d; asm("mul.rn.f32x2 %0, %1, %2;" : "=l"(d) : "l"(a), "l"(b)); return d;
}
__device__ __forceinline__ int reflH(int i) {
    return i < 0 ? -i : (i >= HH ? 2 * HH - 2 - i : i);
}
__device__ __forceinline__ float shup(float v) { return __shfl_up_sync(0xffffffffu, v, 1); }
__device__ __forceinline__ float shdn(float v) { return __shfl_down_sync(0xffffffffu, v, 1); }
__device__ __forceinline__ ulonglong2 ldg4(const float* __restrict__ p, int row) {
    return __ldcs((const ulonglong2*)(p + (size_t)row * WW));
}
__device__ __forceinline__ float ldg1(const float* __restrict__ p, int row, int dq) {
    return __ldg(p + (size_t)row * WW + dq);   // default policy: shared with neighbor strip
}

__global__ __launch_bounds__(NT, 4)
void idwt2d(const float* __restrict__ ss, const float* __restrict__ sd,
            const float* __restrict__ ds, const float* __restrict__ dd,
            const float* __restrict__ hf, const float* __restrict__ gf,
            float* __restrict__ out)
{
    const int lane  = threadIdx.x & 31;
    const int wid   = threadIdx.x >> 5;
    const int strip = wid & 1;                        // 0: cols 0-127, 1: cols 128-255
    const int bc    = blockIdx.z;
    const int r0    = blockIdx.y * (2 * RW) + (wid >> 1) * RW;
    const int c     = strip * 128 + 4 * lane;         // first of 4 owned columns
    const int dq    = (strip ? 127 : 128) - c;        // interior halo column offset

    const size_t base = (size_t)bc * (HH * WW);
    const float* __restrict__ pss = ss + base + c;
    const float* __restrict__ psd = sd + base + c;
    const float* __restrict__ pds = ds + base + c;
    const float* __restrict__ pdd = dd + base + c;
    float* __restrict__ pout = out + (size_t)bc * (4 * HH * WW) + 2 * c;

    u64 H0, H1, H2, H3, H4, H5, G0, G1, G2, G3, G4, G5;
    {
        const float a0 = hf[0], a1 = hf[1], a2 = hf[2], a3 = hf[3], a4 = hf[4], a5 = hf[5];
        const float b0 = gf[0], b1 = gf[1], b2 = gf[2], b3 = gf[3], b4 = gf[4], b5 = gf[5];
        H0 = pk(a0, a0); H1 = pk(a1, a1); H2 = pk(a2, a2);
        H3 = pk(a3, a3); H4 = pk(a4, a4); H5 = pk(a5, a5);
        G0 = pk(b0, b0); G1 = pk(b1, b1); G2 = pk(b2, b2);
        G3 = pk(b3, b3); G4 = pk(b4, b4); G5 = pk(b5, b5);
    }

    // 3-row window: a = row r-1, b = row r, c-slot = row r+1
    ulonglong2 Sa, Sb, Sc, Ta, Tb, Tc, Ua, Ub, Uc, Va, Vb, Vc;
    float hsa, hsb, hsc, hta, htb, htc, hua, hub, huc, hva, hvb, hvc;
    {
        const int rm = reflH(r0 - 1);
        Sa = ldg4(pss, rm); Ta = ldg4(psd, rm); Ua = ldg4(pds, rm); Va = ldg4(pdd, rm);
        hsa = ldg1(pss, rm, dq); hta = ldg1(psd, rm, dq);
        hua = ldg1(pds, rm, dq); hva = ldg1(pdd, rm, dq);
        Sb = ldg4(pss, r0); Tb = ldg4(psd, r0); Ub = ldg4(pds, r0); Vb = ldg4(pdd, r0);
        hsb = ldg1(pss, r0, dq); htb = ldg1(psd, r0, dq);
        hub = ldg1(pds, r0, dq); hvb = ldg1(pdd, r0, dq);
        Sc = ldg4(pss, r0 + 1); Tc = ldg4(psd, r0 + 1); Uc = ldg4(pds, r0 + 1); Vc = ldg4(pdd, r0 + 1);
        hsc = ldg1(pss, r0 + 1, dq); htc = ldg1(psd, r0 + 1, dq);
        huc = ldg1(pds, r0 + 1, dq); hvc = ldg1(pdd, r0 + 1, dq);
    }

    #pragma unroll
    for (int i = 0; i < RW; ++i) {
        const int r = r0 + i;

        // ---- column pass (4 arrays x 2 u64 halves) ----
        const u64 A0x = ffma2(H4, Sa.x, ffma2(H2, Sb.x, ffma2(H0, Sc.x,
                        ffma2(G4, Ta.x, ffma2(G2, Tb.x, fmul2(G0, Tc.x))))));
        const u64 A0y = ffma2(H4, Sa.y, ffma2(H2, Sb.y, ffma2(H0, Sc.y,
                        ffma2(G4, Ta.y, ffma2(G2, Tb.y, fmul2(G0, Tc.y))))));
        const u64 A1x = ffma2(H5, Sa.x, ffma2(H3, Sb.x, ffma2(H1, Sc.x,
                        ffma2(G5, Ta.x, ffma2(G3, Tb.x, fmul2(G1, Tc.x))))));
        const u64 A1y = ffma2(H5, Sa.y, ffma2(H3, Sb.y, ffma2(H1, Sc.y,
                        ffma2(G5, Ta.y, ffma2(G3, Tb.y, fmul2(G1, Tc.y))))));
        const u64 A2x = ffma2(H4, Ua.x, ffma2(H2, Ub.x, ffma2(H0, Uc.x,
                        ffma2(G4, Va.x, ffma2(G2, Vb.x, fmul2(G0, Vc.x))))));
        const u64 A2y = ffma2(H4, Ua.y, ffma2(H2, Ub.y, ffma2(H0, Uc.y,
                        ffma2(G4, Va.y, ffma2(G2, Vb.y, fmul2(G0, Vc.y))))));
        const u64 A3x = ffma2(H5, Ua.x, ffma2(H3, Ub.x, ffma2(H1, Uc.x,
                        ffma2(G5, Va.x, ffma2(G3, Vb.x, fmul2(G1, Vc.x))))));
        const u64 A3y = ffma2(H5, Ua.y, ffma2(H3, Ub.y, ffma2(H1, Uc.y,
                        ffma2(G5, Va.y, ffma2(G3, Vb.y, fmul2(G1, Vc.y))))));

        // halo column pass (packed pairwise: lo = s-side, hi = d-side)
        const u64 P0 = pk(hsa, hua), Q0 = pk(hta, hva);
        const u64 P1 = pk(hsb, hub), Q1 = pk(htb, hvb);
        const u64 P2 = pk(hsc, huc), Q2 = pk(htc, hvc);
        const u64 B02 = ffma2(H4, P0, ffma2(H2, P1, ffma2(H0, P2,
                        ffma2(G4, Q0, ffma2(G2, Q1, fmul2(G0, Q2))))));   // (b0, b2)
        const u64 B13 = ffma2(H5, P0, ffma2(H3, P1, ffma2(H1, P2,
                        ffma2(G5, Q0, ffma2(G3, Q1, fmul2(G1, Q2))))));   // (b1, b3)

        // ---- roll window + load next row (consumed next iteration) ----
        Sa = Sb; Sb = Sc; Ta = Tb; Tb = Tc;
        Ua = Ub; Ub = Uc; Va = Vb; Vb = Vc;
        hsa = hsb; hsb = hsc; hta = htb; htb = htc;
        hua = hub; hub = huc; hva = hvb; hvb = hvc;
        if (i != RW - 1) {
            const int rn = reflH(r + 2);
            Sc = ldg4(pss, rn); Tc = ldg4(psd, rn);
            Uc = ldg4(pds, rn); Vc = ldg4(pdd, rn);
            hsc = ldg1(pss, rn, dq); htc = ldg1(psd, rn, dq);
            huc = ldg1(pds, rn, dq); hvc = ldg1(pdd, rn, dq);
        }

        // ---- row pass ----
        #pragma unroll
        for (int py = 0; py < 2; ++py) {
            const u64 Xa = py ? A1x : A0x, Xb = py ? A1y : A0y;   // sv: {x0,x1},{x2,x3}
            const u64 Ya = py ? A3x : A2x, Yb = py ? A3y : A2y;   // dv
            const u64 B  = py ? B13 : B02;
            const float hx = lof(B), hy = hif(B);

            // v[c-1]: from lane-1's x3; strip0 lane0 -> in-lane v[1], strip1 lane0 -> halo
            float xm1 = shup(hif(Xb)); if (lane == 0)  xm1 = strip ? hx : hif(Xa);
            // v[c+4]: from lane+1's x0; strip0 lane31 -> halo, strip1 lane31 -> in-lane v[254]
            float xp4 = shdn(lof(Xa)); if (lane == 31) xp4 = strip ? lof(Xb) : hx;
            float ym1 = shup(hif(Yb)); if (lane == 0)  ym1 = strip ? hy : hif(Ya);
            float yp4 = shdn(lof(Ya)); if (lane == 31) yp4 = strip ? lof(Yb) : hy;

            const u64 AX = pk(xm1, lof(Xa));        // {x-1, x0}
            const u64 MX = pk(hif(Xa), lof(Xb));    // {x1, x2}  (C of pair01 == A of pair23)
            const u64 CX = pk(hif(Xb), xp4);        // {x3, x4}
            const u64 AY = pk(ym1, lof(Ya));
            const u64 MY = pk(hif(Ya), lof(Yb));
            const u64 CY = pk(hif(Yb), yp4);

            const u64 pe01 = ffma2(H4, AX, ffma2(H2, Xa, ffma2(H0, MX,
                             ffma2(G4, AY, ffma2(G2, Ya, fmul2(G0, MY))))));
            const u64 po01 = ffma2(H5, AX, ffma2(H3, Xa, ffma2(H1, MX,
                             ffma2(G5, AY, ffma2(G3, Ya, fmul2(G1, MY))))));
            const u64 pe23 = ffma2(H4, MX, ffma2(H2, Xb, ffma2(H0, CX,
                             ffma2(G4, MY, ffma2(G2, Yb, fmul2(G0, CY))))));
            const u64 po23 = ffma2(H5, MX, ffma2(H3, Xb, ffma2(H1, CX,
                             ffma2(G5, MY, ffma2(G3, Yb, fmul2(G1, CY))))));

            float e0, e1, f0, f1;
            float* __restrict__ prow = pout + (size_t)(2 * r + py) * (2 * WW);
            unpk(pe01, e0, e1); unpk(po01, f0, f1);
            __stcs((float4*)prow, make_float4(e0, f0, e1, f1));
            unpk(pe23, e0, e1); unpk(po23, f0, f1);
            __stcs((float4*)(prow + 4), make_float4(e0, f0, e1, f1));
        }
    }
}

extern "C" void kernel_launch(void* const* d_in, const int* in_sizes, int n_in,
                              void* d_out, int out_size) {
    const float* ss = (const float*)d_in[0];
    const float* sd = (const float*)d_in[1];
    const float* ds = (const float*)d_in[2];
    const float* dd = (const float*)d_in[3];
    const float* h  = (const float*)d_in[4];
    const float* g  = (const float*)d_in[5];
    float* out = (float*)d_out;

    dim3 grid(1, HH / (2 * RW), 4 * 64);   // (1, 8, 256) = 2048 blocks x 4 warps
    idwt2d<<<grid, NT>>>(ss, sd, ds, dd, h, g, out);
}

// round 16
// speedup vs baseline: 1.3099x; 1.0098x over previous
#include <cuda_runtime.h>

// Inverse 2D DWT, single level. (4,64,256,256) f32 x4 subbands -> (4,64,512,512) f32.
// FINAL — champion configuration (R9, 94.27us / 5.74 TB/s, DRAM-efficiency-limited):
// Warp-autonomous, LDG.128: one warp owns a 128-col strip x RW rows; each lane owns
// 4 adjacent columns (one ulonglong2 = 2 f32x2 per subband-row).
//  - Rolling 3-row window; next row's loads issued right after the column pass
//    (hidden under the row pass). Reads 512B contiguous per warp-request, writes 1KB.
//  - W-edge reflection is in-lane (v[-1]=v[1], v[256]=v[254] are owned columns);
//    ONE interior halo column per strip (broadcast scalar loads).
//  - All math packed fp32x2 (FFMA2): 48 FFMA2/lane per 2x8 output block.
//  - Streaming cache hints (.cs) on all touch-once data. No smem, no barriers.
//  - Full unroll (validated: partial unroll degrades load-use distance).

#define HH 256
#define WW 256
#define RW 16
#define NT 128

typedef unsigned long long u64;

__device__ __forceinline__ u64 pk(float lo, float hi) {
    u64 r; asm("mov.b64 %0, {%1, %2};" : "=l"(r) : "f"(lo), "f"(hi)); return r;
}
__device__ __forceinline__ void unpk(u64 v, float& lo, float& hi) {
    asm("mov.b64 {%0, %1}, %2;" : "=f"(lo), "=f"(hi) : "l"(v));
}
__device__ __forceinline__ float lof(u64 v) { float a, b; unpk(v, a, b); return a; }
__device__ __forceinline__ float hif(u64 v) { float a, b; unpk(v, a, b); return b; }
__device__ __forceinline__ u64 ffma2(u64 a, u64 b, u64 c) {
    u64 d; asm("fma.rn.f32x2 %0, %1, %2, %3;" : "=l"(d) : "l"(a), "l"(b), "l"(c)); return d;
}
__device__ __forceinline__ u64 fmul2(u64 a, u64 b) {
    u64 d; asm("mul.rn.f32x2 %0, %1, %2;" : "=l"(d) : "l"(a), "l"(b)); return d;
}
__device__ __forceinline__ int reflH(int i) {
    return i < 0 ? -i : (i >= HH ? 2 * HH - 2 - i : i);
}
__device__ __forceinline__ float shup(float v) { return __shfl_up_sync(0xffffffffu, v, 1); }
__device__ __forceinline__ float shdn(float v) { return __shfl_down_sync(0xffffffffu, v, 1); }
__device__ __forceinline__ ulonglong2 ldg4(const float* __restrict__ p, int row) {
    return __ldcs((const ulonglong2*)(p + (size_t)row * WW));
}
__device__ __forceinline__ float ldg1(const float* __restrict__ p, int row, int dq) {
    return __ldcs(p + (size_t)row * WW + dq);
}

__global__ __launch_bounds__(NT, 4)
void idwt2d(const float* __restrict__ ss, const float* __restrict__ sd,
            const float* __restrict__ ds, const float* __restrict__ dd,
            const float* __restrict__ hf, const float* __restrict__ gf,
            float* __restrict__ out)
{
    const int lane  = threadIdx.x & 31;
    const int wid   = threadIdx.x >> 5;
    const int strip = wid & 1;                        // 0: cols 0-127, 1: cols 128-255
    const int bc    = blockIdx.z;
    const int r0    = blockIdx.y * (2 * RW) + (wid >> 1) * RW;
    const int c     = strip * 128 + 4 * lane;         // first of 4 owned columns
    const int dq    = (strip ? 127 : 128) - c;        // interior halo column offset

    const size_t base = (size_t)bc * (HH * WW);
    const float* __restrict__ pss = ss + base + c;
    const float* __restrict__ psd = sd + base + c;
    const float* __restrict__ pds = ds + base + c;
    const float* __restrict__ pdd = dd + base + c;
    float* __restrict__ pout = out + (size_t)bc * (4 * HH * WW) + 2 * c;

    u64 H0, H1, H2, H3, H4, H5, G0, G1, G2, G3, G4, G5;
    {
        const float a0 = hf[0], a1 = hf[1], a2 = hf[2], a3 = hf[3], a4 = hf[4], a5 = hf[5];
        const float b0 = gf[0], b1 = gf[1], b2 = gf[2], b3 = gf[3], b4 = gf[4], b5 = gf[5];
        H0 = pk(a0, a0); H1 = pk(a1, a1); H2 = pk(a2, a2);
        H3 = pk(a3, a3); H4 = pk(a4, a4); H5 = pk(a5, a5);
        G0 = pk(b0, b0); G1 = pk(b1, b1); G2 = pk(b2, b2);
        G3 = pk(b3, b3); G4 = pk(b4, b4); G5 = pk(b5, b5);
    }

    // 3-row window: a = row r-1, b = row r, c-slot = row r+1
    ulonglong2 Sa, Sb, Sc, Ta, Tb, Tc, Ua, Ub, Uc, Va, Vb, Vc;
    float hsa, hsb, hsc, hta, htb, htc, hua, hub, huc, hva, hvb, hvc;
    {
        const int rm = reflH(r0 - 1);
        Sa = ldg4(pss, rm); Ta = ldg4(psd, rm); Ua = ldg4(pds, rm); Va = ldg4(pdd, rm);
        hsa = ldg1(pss, rm, dq); hta = ldg1(psd, rm, dq);
        hua = ldg1(pds, rm, dq); hva = ldg1(pdd, rm, dq);
        Sb = ldg4(pss, r0); Tb = ldg4(psd, r0); Ub = ldg4(pds, r0); Vb = ldg4(pdd, r0);
        hsb = ldg1(pss, r0, dq); htb = ldg1(psd, r0, dq);
        hub = ldg1(pds, r0, dq); hvb = ldg1(pdd, r0, dq);
        Sc = ldg4(pss, r0 + 1); Tc = ldg4(psd, r0 + 1); Uc = ldg4(pds, r0 + 1); Vc = ldg4(pdd, r0 + 1);
        hsc = ldg1(pss, r0 + 1, dq); htc = ldg1(psd, r0 + 1, dq);
        huc = ldg1(pds, r0 + 1, dq); hvc = ldg1(pdd, r0 + 1, dq);
    }

    #pragma unroll
    for (int i = 0; i < RW; ++i) {
        const int r = r0 + i;

        // ---- column pass (4 arrays x 2 u64 halves) ----
        const u64 A0x = ffma2(H4, Sa.x, ffma2(H2, Sb.x, ffma2(H0, Sc.x,
                        ffma2(G4, Ta.x, ffma2(G2, Tb.x, fmul2(G0, Tc.x))))));
        const u64 A0y = ffma2(H4, Sa.y, ffma2(H2, Sb.y, ffma2(H0, Sc.y,
                        ffma2(G4, Ta.y, ffma2(G2, Tb.y, fmul2(G0, Tc.y))))));
        const u64 A1x = ffma2(H5, Sa.x, ffma2(H3, Sb.x, ffma2(H1, Sc.x,
                        ffma2(G5, Ta.x, ffma2(G3, Tb.x, fmul2(G1, Tc.x))))));
        const u64 A1y = ffma2(H5, Sa.y, ffma2(H3, Sb.y, ffma2(H1, Sc.y,
                        ffma2(G5, Ta.y, ffma2(G3, Tb.y, fmul2(G1, Tc.y))))));
        const u64 A2x = ffma2(H4, Ua.x, ffma2(H2, Ub.x, ffma2(H0, Uc.x,
                        ffma2(G4, Va.x, ffma2(G2, Vb.x, fmul2(G0, Vc.x))))));
        const u64 A2y = ffma2(H4, Ua.y, ffma2(H2, Ub.y, ffma2(H0, Uc.y,
                        ffma2(G4, Va.y, ffma2(G2, Vb.y, fmul2(G0, Vc.y))))));
        const u64 A3x = ffma2(H5, Ua.x, ffma2(H3, Ub.x, ffma2(H1, Uc.x,
                        ffma2(G5, Va.x, ffma2(G3, Vb.x, fmul2(G1, Vc.x))))));
        const u64 A3y = ffma2(H5, Ua.y, ffma2(H3, Ub.y, ffma2(H1, Uc.y,
                        ffma2(G5, Va.y, ffma2(G3, Vb.y, fmul2(G1, Vc.y))))));

        // halo column pass (packed pairwise: lo = s-side, hi = d-side)
        const u64 P0 = pk(hsa, hua), Q0 = pk(hta, hva);
        const u64 P1 = pk(hsb, hub), Q1 = pk(htb, hvb);
        const u64 P2 = pk(hsc, huc), Q2 = pk(htc, hvc);
        const u64 B02 = ffma2(H4, P0, ffma2(H2, P1, ffma2(H0, P2,
                        ffma2(G4, Q0, ffma2(G2, Q1, fmul2(G0, Q2))))));   // (b0, b2)
        const u64 B13 = ffma2(H5, P0, ffma2(H3, P1, ffma2(H1, P2,
                        ffma2(G5, Q0, ffma2(G3, Q1, fmul2(G1, Q2))))));   // (b1, b3)

        // ---- roll window + load next row (consumed next iteration) ----
        Sa = Sb; Sb = Sc; Ta = Tb; Tb = Tc;
        Ua = Ub; Ub = Uc; Va = Vb; Vb = Vc;
        hsa = hsb; hsb = hsc; hta = htb; htb = htc;
        hua = hub; hub = huc; hva = hvb; hvb = hvc;
        if (i != RW - 1) {
            const int rn = reflH(r + 2);
            Sc = ldg4(pss, rn); Tc = ldg4(psd, rn);
            Uc = ldg4(pds, rn); Vc = ldg4(pdd, rn);
            hsc = ldg1(pss, rn, dq); htc = ldg1(psd, rn, dq);
            huc = ldg1(pds, rn, dq); hvc = ldg1(pdd, rn, dq);
        }

        // ---- row pass ----
        #pragma unroll
        for (int py = 0; py < 2; ++py) {
            const u64 Xa = py ? A1x : A0x, Xb = py ? A1y : A0y;   // sv: {x0,x1},{x2,x3}
            const u64 Ya = py ? A3x : A2x, Yb = py ? A3y : A2y;   // dv
            const u64 B  = py ? B13 : B02;
            const float hx = lof(B), hy = hif(B);

            // v[c-1]: from lane-1's x3; strip0 lane0 -> in-lane v[1], strip1 lane0 -> halo
            float xm1 = shup(hif(Xb)); if (lane == 0)  xm1 = strip ? hx : hif(Xa);
            // v[c+4]: from lane+1's x0; strip0 lane31 -> halo, strip1 lane31 -> in-lane v[254]
            float xp4 = shdn(lof(Xa)); if (lane == 31) xp4 = strip ? lof(Xb) : hx;
            float ym1 = shup(hif(Yb)); if (lane == 0)  ym1 = strip ? hy : hif(Ya);
            float yp4 = shdn(lof(Ya)); if (lane == 31) yp4 = strip ? lof(Yb) : hy;

            const u64 AX = pk(xm1, lof(Xa));        // {x-1, x0}
            const u64 MX = pk(hif(Xa), lof(Xb));    // {x1, x2}  (C of pair01 == A of pair23)
            const u64 CX = pk(hif(Xb), xp4);        // {x3, x4}
            const u64 AY = pk(ym1, lof(Ya));
            const u64 MY = pk(hif(Ya), lof(Yb));
            const u64 CY = pk(hif(Yb), yp4);

            const u64 pe01 = ffma2(H4, AX, ffma2(H2, Xa, ffma2(H0, MX,
                             ffma2(G4, AY, ffma2(G2, Ya, fmul2(G0, MY))))));
            const u64 po01 = ffma2(H5, AX, ffma2(H3, Xa, ffma2(H1, MX,
                             ffma2(G5, AY, ffma2(G3, Ya, fmul2(G1, MY))))));
            const u64 pe23 = ffma2(H4, MX, ffma2(H2, Xb, ffma2(H0, CX,
                             ffma2(G4, MY, ffma2(G2, Yb, fmul2(G0, CY))))));
            const u64 po23 = ffma2(H5, MX, ffma2(H3, Xb, ffma2(H1, CX,
                             ffma2(G5, MY, ffma2(G3, Yb, fmul2(G1, CY))))));

            float e0, e1, f0, f1;
            float* __restrict__ prow = pout + (size_t)(2 * r + py) * (2 * WW);
            unpk(pe01, e0, e1); unpk(po01, f0, f1);
            __stcs((float4*)prow, make_float4(e0, f0, e1, f1));
            unpk(pe23, e0, e1); unpk(po23, f0, f1);
            __stcs((float4*)(prow + 4), make_float4(e0, f0, e1, f1));
        }
    }
}

extern "C" void kernel_launch(void* const* d_in, const int* in_sizes, int n_in,
                              void* d_out, int out_size) {
    const float* ss = (const float*)d_in[0];
    const float* sd = (const float*)d_in[1];
    const float* ds = (const float*)d_in[2];
    const float* dd = (const float*)d_in[3];
    const float* h  = (const float*)d_in[4];
    const float* g  = (const float*)d_in[5];
    float* out = (float*)d_out;

    dim3 grid(1, HH / (2 * RW), 4 * 64);   // (1, 8, 256) = 2048 blocks x 4 warps
    idwt2d<<<grid, NT>>>(ss, sd, ds, dd, h, g, out);
}